// round 9
// baseline (speedup 1.0000x reference)
#include <cuda_runtime.h>
#include <cuda_bf16.h>
#include <cstdint>

#define D 256
#define MAXM 100096   // >= N, multiple of 128
#define MAXE 1700000
#define SCANB 1024
#define MAXSB 128

// ---------------- scratch (device globals; no allocations) ----------------
__device__ float g_t[(size_t)MAXM * D];   // aggregated features (GEMM-a input)
__device__ float g_u[(size_t)MAXM * D];   // GEMM-a output
__device__ float g_hbuf[(size_t)MAXM * D];// conv1 output
__device__ float g_sum[D];
__device__ float g_sumsq[D];
__device__ float g_scale[D];
__device__ float g_shift[D];
// weights pre-converted to bf16 hi/lo: 4 matrices of 256x256
__device__ __nv_bfloat16 g_wh[4][D * D];
__device__ __nv_bfloat16 g_wl[4][D * D];
// CSR scratch
__device__ int g_deg[MAXM];
__device__ int g_cursor[MAXM];
__device__ int g_rowptr[MAXM + 1];
__device__ int g_col[MAXE];
__device__ int g_bsum[MAXSB];

// ---------------- BN helpers ----------------
__global__ void zero_stats_kernel() {
    g_sum[threadIdx.x] = 0.f;
    g_sumsq[threadIdx.x] = 0.f;
}

__global__ void stats_kernel(const float* __restrict__ X, int M) {
    int c = threadIdx.x;
    int rows = (M + gridDim.x - 1) / gridDim.x;
    int r0 = blockIdx.x * rows;
    int r1 = r0 + rows;
    if (r1 > M) r1 = M;
    float s = 0.f, q = 0.f;
    int r = r0;
    for (; r + 4 <= r1; r += 4) {
        float v0 = X[(size_t)(r + 0) * D + c];
        float v1 = X[(size_t)(r + 1) * D + c];
        float v2 = X[(size_t)(r + 2) * D + c];
        float v3 = X[(size_t)(r + 3) * D + c];
        s += (v0 + v1) + (v2 + v3);
        q += (v0 * v0 + v1 * v1) + (v2 * v2 + v3 * v3);
    }
    for (; r < r1; r++) {
        float v = X[(size_t)r * D + c];
        s += v;
        q += v * v;
    }
    if (r1 > r0) {
        atomicAdd(&g_sum[c], s);
        atomicAdd(&g_sumsq[c], q);
    }
}

__global__ void finalize_stats_kernel(const float* __restrict__ gamma,
                                      const float* __restrict__ beta, int M) {
    int c = threadIdx.x;
    float invM = 1.f / (float)M;
    float mu = g_sum[c] * invM;
    float var = g_sumsq[c] * invM - mu * mu;
    float sc = gamma[c] * rsqrtf(var + 1e-5f);
    g_scale[c] = sc;
    g_shift[c] = beta[c] - mu * sc;
}

// ---------------- weight pre-conversion (bf16 hi/lo split) ----------------
__global__ void convert_w_kernel(const float* __restrict__ W,
                                 __nv_bfloat16* __restrict__ Wh,
                                 __nv_bfloat16* __restrict__ Wl) {
    int i = blockIdx.x * blockDim.x + threadIdx.x;
    float2 v = ((const float2*)W)[i];
    __nv_bfloat162 hh = __floats2bfloat162_rn(v.x, v.y);
    float2 f = __bfloat1622float2(hh);
    __nv_bfloat162 ll = __floats2bfloat162_rn(v.x - f.x, v.y - f.y);
    ((__nv_bfloat162*)Wh)[i] = hh;
    ((__nv_bfloat162*)Wl)[i] = ll;
}

// ---------------- CSR build ----------------
__global__ void zero_deg_kernel(int M) {
    int i = blockIdx.x * blockDim.x + threadIdx.x;
    if (i < M) {
        g_deg[i] = 0;
        g_cursor[i] = 0;
    }
}

__global__ void hist_kernel(const int* __restrict__ dstIdx, int E) {
    int e = blockIdx.x * blockDim.x + threadIdx.x;
    if (e < E) atomicAdd(&g_deg[dstIdx[e]], 1);
}

__global__ void scan_block_kernel(int M) {
    __shared__ int sh[SCANB];
    int i = blockIdx.x * SCANB + threadIdx.x;
    int v = (i < M) ? g_deg[i] : 0;
    sh[threadIdx.x] = v;
    __syncthreads();
    for (int off = 1; off < SCANB; off <<= 1) {
        int t = (threadIdx.x >= off) ? sh[threadIdx.x - off] : 0;
        __syncthreads();
        sh[threadIdx.x] += t;
        __syncthreads();
    }
    if (i < M) g_rowptr[i] = sh[threadIdx.x] - v;
    if (threadIdx.x == SCANB - 1) g_bsum[blockIdx.x] = sh[SCANB - 1];
}

__global__ void scan_bsum_kernel(int nb) {
    if (threadIdx.x == 0) {
        int run = 0;
        for (int i = 0; i < nb; i++) {
            int v = g_bsum[i];
            g_bsum[i] = run;
            run += v;
        }
    }
}

__global__ void scan_add_kernel(int M, int E) {
    int i = blockIdx.x * SCANB + threadIdx.x;
    if (i < M) g_rowptr[i] += g_bsum[blockIdx.x];
    if (i == 0) g_rowptr[M] = E;
}

__global__ void fill_kernel(const int* __restrict__ srcIdx,
                            const int* __restrict__ dstIdx, int E) {
    int e = blockIdx.x * blockDim.x + threadIdx.x;
    if (e >= E) return;
    int d = dstIdx[e];
    int pos = g_rowptr[d] + atomicAdd(&g_cursor[d], 1);
    g_col[pos] = srcIdx[e];
}

// ---------------- CSR aggregation ----------------
template <int BN_FOLD>
__global__ void agg_csr_kernel(const float* __restrict__ feat,
                               float* __restrict__ out, int M) {
    int node = blockIdx.x * 4 + (threadIdx.x >> 6);
    if (node >= M) return;
    int lane = threadIdx.x & 63;
    int e0 = __ldg(&g_rowptr[node]);
    int e1 = __ldg(&g_rowptr[node + 1]);
    const float4* base = (const float4*)feat;
    float4 acc = base[(size_t)node * 64 + lane];  // self term
    int e = e0;
    for (; e + 4 <= e1; e += 4) {
        int s0 = __ldg(&g_col[e + 0]);
        int s1 = __ldg(&g_col[e + 1]);
        int s2 = __ldg(&g_col[e + 2]);
        int s3 = __ldg(&g_col[e + 3]);
        float4 v0 = base[(size_t)s0 * 64 + lane];
        float4 v1 = base[(size_t)s1 * 64 + lane];
        float4 v2 = base[(size_t)s2 * 64 + lane];
        float4 v3 = base[(size_t)s3 * 64 + lane];
        acc.x += (v0.x + v1.x) + (v2.x + v3.x);
        acc.y += (v0.y + v1.y) + (v2.y + v3.y);
        acc.z += (v0.z + v1.z) + (v2.z + v3.z);
        acc.w += (v0.w + v1.w) + (v2.w + v3.w);
    }
    for (; e < e1; e++) {
        int s = __ldg(&g_col[e]);
        float4 v = base[(size_t)s * 64 + lane];
        acc.x += v.x;
        acc.y += v.y;
        acc.z += v.z;
        acc.w += v.w;
    }
    if (BN_FOLD) {
        float4 s = ((const float4*)g_scale)[lane];
        float4 sh = ((const float4*)g_shift)[lane];
        float k = (float)(1 + (e1 - e0));
        acc.x = acc.x * s.x + k * sh.x;
        acc.y = acc.y * s.y + k * sh.y;
        acc.z = acc.z * s.z + k * sh.z;
        acc.w = acc.w * s.w + k * sh.w;
    }
    ((float4*)out)[(size_t)node * 64 + lane] = acc;
}

// ---------------- tensor-core GEMM (bf16x3 split, fp32 accum) ----------------
// Software-pipelined: B via cp.async double-buffer, A via register prefetch.
#define BK 32
#define AS 40    // As row stride (elements)
#define BS 136   // Bs row stride (elements)
#define NKT (D / BK)          // 8 k-tiles
#define AS_TILE (128 * AS)    // elems per As buffer
#define BS_TILE (BK * BS)     // elems per Bs buffer
// dynamic smem: As_h[2], As_l[2], Bs_h[2], Bs_l[2]
#define SMEM_ELEMS (4 * AS_TILE + 4 * BS_TILE)
#define SMEM_BYTES (SMEM_ELEMS * 2)

template <int BN_IN, int RELU>
__global__ __launch_bounds__(256, 1) void gemm_tc_kernel(
    const float* __restrict__ A, const __nv_bfloat16* __restrict__ Wh,
    const __nv_bfloat16* __restrict__ Wl, const float* __restrict__ bias,
    float* __restrict__ C, int M) {
    extern __shared__ __nv_bfloat16 smem[];
    __nv_bfloat16* As_h = smem;                       // [2][AS_TILE]
    __nv_bfloat16* As_l = As_h + 2 * AS_TILE;         // [2][AS_TILE]
    __nv_bfloat16* Bs_h = As_l + 2 * AS_TILE;         // [2][BS_TILE]
    __nv_bfloat16* Bs_l = Bs_h + 2 * BS_TILE;         // [2][BS_TILE]

    int bm = blockIdx.x * 128;
    int bn = blockIdx.y * 128;
    int tid = threadIdx.x;
    int lane = tid & 31;
    int wid = tid >> 5;
    int warp_m = wid >> 2;   // 0..1
    int warp_n = wid & 3;    // 0..3

    float acc[4][4][4];
#pragma unroll
    for (int i = 0; i < 4; i++)
#pragma unroll
        for (int j = 0; j < 4; j++)
#pragma unroll
            for (int r = 0; r < 4; r++) acc[i][j][r] = 0.f;

    int a_row = tid >> 1;
    int a_kb = (tid & 1) * 16;
    bool a_valid = (bm + a_row) < M;

    uint32_t as_h_base = (uint32_t)__cvta_generic_to_shared(As_h);
    uint32_t as_l_base = (uint32_t)__cvta_generic_to_shared(As_l);
    uint32_t bs_h_base = (uint32_t)__cvta_generic_to_shared(Bs_h);
    uint32_t bs_l_base = (uint32_t)__cvta_generic_to_shared(Bs_l);

    float4 areg[4];  // prefetched A tile (16 k-floats per thread)

    auto load_a = [&](int k0) {
        const float* Ar = A + (size_t)(bm + a_row) * D + k0 + a_kb;
#pragma unroll
        for (int i = 0; i < 4; i++)
            areg[i] = a_valid ? *(const float4*)(Ar + i * 4)
                              : make_float4(0.f, 0.f, 0.f, 0.f);
    };

    auto store_a = [&](int buf, int k0) {
        __nv_bfloat16* dst_h = As_h + buf * AS_TILE;
        __nv_bfloat16* dst_l = As_l + buf * AS_TILE;
#pragma unroll
        for (int i = 0; i < 4; i++) {
            float4 v = areg[i];
            if (BN_IN) {
                float4 s = ((const float4*)g_scale)[((k0 + a_kb) >> 2) + i];
                float4 sh = ((const float4*)g_shift)[((k0 + a_kb) >> 2) + i];
                v.x = fmaxf(v.x * s.x + sh.x, 0.f);
                v.y = fmaxf(v.y * s.y + sh.y, 0.f);
                v.z = fmaxf(v.z * s.z + sh.z, 0.f);
                v.w = fmaxf(v.w * s.w + sh.w, 0.f);
            }
            __nv_bfloat162 h01 = __floats2bfloat162_rn(v.x, v.y);
            __nv_bfloat162 h23 = __floats2bfloat162_rn(v.z, v.w);
            float2 f01 = __bfloat1622float2(h01);
            float2 f23 = __bfloat1622float2(h23);
            __nv_bfloat162 l01 = __floats2bfloat162_rn(v.x - f01.x, v.y - f01.y);
            __nv_bfloat162 l23 = __floats2bfloat162_rn(v.z - f23.x, v.w - f23.y);
            int off = a_row * AS + a_kb + i * 4;
            *(__nv_bfloat162*)&dst_h[off] = h01;
            *(__nv_bfloat162*)&dst_h[off + 2] = h23;
            *(__nv_bfloat162*)&dst_l[off] = l01;
            *(__nv_bfloat162*)&dst_l[off + 2] = l23;
        }
    };

    auto cp_b = [&](int k0, int buf) {
#pragma unroll
        for (int rep = 0; rep < 2; rep++) {
            int j = tid + rep * 256;     // 0..511
            int row = j >> 4;            // 0..31
            int c8 = (j & 15) * 8;       // 0..120
            size_t goff = (size_t)(k0 + row) * D + bn + c8;
            uint32_t dh = bs_h_base + (uint32_t)(buf * BS_TILE + row * BS + c8) * 2;
            uint32_t dl = bs_l_base + (uint32_t)(buf * BS_TILE + row * BS + c8) * 2;
            asm volatile("cp.async.cg.shared.global [%0], [%1], 16;\n"
                         :: "r"(dh), "l"(Wh + goff));
            asm volatile("cp.async.cg.shared.global [%0], [%1], 16;\n"
                         :: "r"(dl), "l"(Wl + goff));
        }
        asm volatile("cp.async.commit_group;\n" ::: "memory");
    };

    auto compute = [&](int buf) {
        uint32_t ahb = as_h_base + (uint32_t)(buf * AS_TILE) * 2;
        uint32_t alb = as_l_base + (uint32_t)(buf * AS_TILE) * 2;
        uint32_t bhb = bs_h_base + (uint32_t)(buf * BS_TILE) * 2;
        uint32_t blb = bs_l_base + (uint32_t)(buf * BS_TILE) * 2;
#pragma unroll
        for (int k16 = 0; k16 < BK; k16 += 16) {
            uint32_t ah[4][4];
            uint32_t al[4][4];
            uint32_t bh[4][2];
            uint32_t bl[4][2];
#pragma unroll
            for (int mi = 0; mi < 4; mi++) {
                int row = warp_m * 64 + mi * 16 + (lane & 15);
                int col = k16 + ((lane >> 4) << 3);
                uint32_t ad = ahb + (uint32_t)(row * AS + col) * 2;
                asm volatile("ldmatrix.sync.aligned.m8n8.x4.shared.b16 {%0,%1,%2,%3}, [%4];"
                             : "=r"(ah[mi][0]), "=r"(ah[mi][1]), "=r"(ah[mi][2]), "=r"(ah[mi][3])
                             : "r"(ad));
                uint32_t ad2 = alb + (uint32_t)(row * AS + col) * 2;
                asm volatile("ldmatrix.sync.aligned.m8n8.x4.shared.b16 {%0,%1,%2,%3}, [%4];"
                             : "=r"(al[mi][0]), "=r"(al[mi][1]), "=r"(al[mi][2]), "=r"(al[mi][3])
                             : "r"(ad2));
            }
#pragma unroll
            for (int ni = 0; ni < 4; ni++) {
                int row = k16 + (lane & 15);
                int col = warp_n * 32 + ni * 8;
                uint32_t bd = bhb + (uint32_t)(row * BS + col) * 2;
                asm volatile("ldmatrix.sync.aligned.m8n8.x2.trans.shared.b16 {%0,%1}, [%2];"
                             : "=r"(bh[ni][0]), "=r"(bh[ni][1]) : "r"(bd));
                uint32_t bd2 = blb + (uint32_t)(row * BS + col) * 2;
                asm volatile("ldmatrix.sync.aligned.m8n8.x2.trans.shared.b16 {%0,%1}, [%2];"
                             : "=r"(bl[ni][0]), "=r"(bl[ni][1]) : "r"(bd2));
            }
#pragma unroll
            for (int mi = 0; mi < 4; mi++) {
#pragma unroll
                for (int ni = 0; ni < 4; ni++) {
                    float* d = acc[mi][ni];
                    asm volatile(
                        "mma.sync.aligned.m16n8k16.row.col.f32.bf16.bf16.f32 "
                        "{%0,%1,%2,%3}, {%4,%5,%6,%7}, {%8,%9}, {%0,%1,%2,%3};"
                        : "+f"(d[0]), "+f"(d[1]), "+f"(d[2]), "+f"(d[3])
                        : "r"(ah[mi][0]), "r"(ah[mi][1]), "r"(ah[mi][2]), "r"(ah[mi][3]),
                          "r"(bh[ni][0]), "r"(bh[ni][1]));
                    asm volatile(
                        "mma.sync.aligned.m16n8k16.row.col.f32.bf16.bf16.f32 "
                        "{%0,%1,%2,%3}, {%4,%5,%6,%7}, {%8,%9}, {%0,%1,%2,%3};"
                        : "+f"(d[0]), "+f"(d[1]), "+f"(d[2]), "+f"(d[3])
                        : "r"(ah[mi][0]), "r"(ah[mi][1]), "r"(ah[mi][2]), "r"(ah[mi][3]),
                          "r"(bl[ni][0]), "r"(bl[ni][1]));
                    asm volatile(
                        "mma.sync.aligned.m16n8k16.row.col.f32.bf16.bf16.f32 "
                        "{%0,%1,%2,%3}, {%4,%5,%6,%7}, {%8,%9}, {%0,%1,%2,%3};"
                        : "+f"(d[0]), "+f"(d[1]), "+f"(d[2]), "+f"(d[3])
                        : "r"(al[mi][0]), "r"(al[mi][1]), "r"(al[mi][2]), "r"(al[mi][3]),
                          "r"(bh[ni][0]), "r"(bh[ni][1]));
                }
            }
        }
    };

    // ---- pipelined mainloop ----
    load_a(0);
    store_a(0, 0);
    cp_b(0, 0);
    load_a(BK);                 // prefetch tile 1 into regs
    asm volatile("cp.async.wait_group 0;\n" ::: "memory");
    __syncthreads();

#pragma unroll 2
    for (int kt = 0; kt < NKT; kt++) {
        int cur = kt & 1;
        int nxt = cur ^ 1;
        if (kt + 1 < NKT) {
            cp_b((kt + 1) * BK, nxt);      // async fill of next B buffer
            store_a(nxt, (kt + 1) * BK);   // convert prefetched A into next buffer
            if (kt + 2 < NKT) load_a((kt + 2) * BK);  // issue A loads 2 ahead
        }
        compute(cur);
        if (kt + 1 < NKT) {
            asm volatile("cp.async.wait_group 0;\n" ::: "memory");
            __syncthreads();
        }
    }

    // ---- epilogue: bias (+relu) + store ----
#pragma unroll
    for (int mi = 0; mi < 4; mi++) {
#pragma unroll
        for (int ni = 0; ni < 4; ni++) {
            int r0 = bm + warp_m * 64 + mi * 16 + (lane >> 2);
            int c0 = bn + warp_n * 32 + ni * 8 + (lane & 3) * 2;
            float b0 = bias[c0], b1 = bias[c0 + 1];
            float* d = acc[mi][ni];
            float2 v0 = make_float2(d[0] + b0, d[1] + b1);
            float2 v1 = make_float2(d[2] + b0, d[3] + b1);
            if (RELU) {
                v0.x = fmaxf(v0.x, 0.f); v0.y = fmaxf(v0.y, 0.f);
                v1.x = fmaxf(v1.x, 0.f); v1.y = fmaxf(v1.y, 0.f);
            }
            if (r0 < M) *(float2*)&C[(size_t)r0 * D + c0] = v0;
            if (r0 + 8 < M) *(float2*)&C[(size_t)(r0 + 8) * D + c0] = v1;
        }
    }
}

// ---------------- driver ----------------
extern "C" void kernel_launch(void* const* d_in, const int* in_sizes, int n_in,
                              void* d_out, int out_size) {
    const float* x = (const float*)d_in[0];
    const int* ei = (const int*)d_in[1];   // int32 (JAX x64 disabled)
    const float* g0 = (const float*)d_in[2];
    const float* b0 = (const float*)d_in[3];
    const float* W1a = (const float*)d_in[4];
    const float* b1a = (const float*)d_in[5];
    const float* g1 = (const float*)d_in[6];
    const float* bt1 = (const float*)d_in[7];
    const float* W1b = (const float*)d_in[8];
    const float* b1b = (const float*)d_in[9];
    const float* W2a = (const float*)d_in[10];
    const float* b2a = (const float*)d_in[11];
    const float* g2 = (const float*)d_in[12];
    const float* bt2 = (const float*)d_in[13];
    const float* W2b = (const float*)d_in[14];
    const float* b2b = (const float*)d_in[15];
    float* out = (float*)d_out;

    int M = in_sizes[0] / D;
    int E = in_sizes[1] / 2;
    const int* srcI = ei;
    const int* dstI = ei + E;

    float *t, *u, *h;
    cudaGetSymbolAddress((void**)&t, g_t);
    cudaGetSymbolAddress((void**)&u, g_u);
    cudaGetSymbolAddress((void**)&h, g_hbuf);
    __nv_bfloat16 *wh, *wl;
    cudaGetSymbolAddress((void**)&wh, g_wh);
    cudaGetSymbolAddress((void**)&wl, g_wl);
    __nv_bfloat16* Wh[4] = {wh, wh + D * D, wh + 2 * D * D, wh + 3 * D * D};
    __nv_bfloat16* Wl[4] = {wl, wl + D * D, wl + 2 * D * D, wl + 3 * D * D};

    static int attr_done = 0;
    if (!attr_done) {
        cudaFuncSetAttribute(gemm_tc_kernel<0, 0>,
                             cudaFuncAttributeMaxDynamicSharedMemorySize, SMEM_BYTES);
        cudaFuncSetAttribute(gemm_tc_kernel<1, 1>,
                             cudaFuncAttributeMaxDynamicSharedMemorySize, SMEM_BYTES);
        attr_done = 1;
    }

    dim3 gemmGrid((M + 127) / 128, 2);
    int aggGrid = (M + 3) / 4;
    int nb = (M + SCANB - 1) / SCANB;
    int cwGrid = (D * D / 2) / 256;

    // ---- pre-convert weights (once per launch) ----
    convert_w_kernel<<<cwGrid, 256>>>(W1a, Wh[0], Wl[0]);
    convert_w_kernel<<<cwGrid, 256>>>(W1b, Wh[1], Wl[1]);
    convert_w_kernel<<<cwGrid, 256>>>(W2a, Wh[2], Wl[2]);
    convert_w_kernel<<<cwGrid, 256>>>(W2b, Wh[3], Wl[3]);

    // ---- build CSR once (reused by both convs) ----
    zero_deg_kernel<<<(M + 255) / 256, 256>>>(M);
    hist_kernel<<<(E + 255) / 256, 256>>>(dstI, E);
    scan_block_kernel<<<nb, SCANB>>>(M);
    scan_bsum_kernel<<<1, 32>>>(nb);
    scan_add_kernel<<<nb, SCANB>>>(M, E);
    fill_kernel<<<(E + 255) / 256, 256>>>(srcI, dstI, E);

    // ---- BN0 stats on x; agg with BN folded (linearity) ----
    zero_stats_kernel<<<1, 256>>>();
    stats_kernel<<<512, 256>>>(x, M);
    finalize_stats_kernel<<<1, 256>>>(g0, b0, M);
    agg_csr_kernel<1><<<aggGrid, 256>>>(x, t, M);                       // t = BN0-agg(x)

    // ---- conv1 ----
    gemm_tc_kernel<0, 0><<<gemmGrid, 256, SMEM_BYTES>>>(t, Wh[0], Wl[0], b1a, u, M);
    zero_stats_kernel<<<1, 256>>>();
    stats_kernel<<<512, 256>>>(u, M);
    finalize_stats_kernel<<<1, 256>>>(g1, bt1, M);
    gemm_tc_kernel<1, 1><<<gemmGrid, 256, SMEM_BYTES>>>(u, Wh[1], Wl[1], b1b, h, M);

    // ---- conv2 ----
    agg_csr_kernel<0><<<aggGrid, 256>>>(h, t, M);                       // t = h + Σh
    gemm_tc_kernel<0, 0><<<gemmGrid, 256, SMEM_BYTES>>>(t, Wh[2], Wl[2], b2a, u, M);
    zero_stats_kernel<<<1, 256>>>();
    stats_kernel<<<512, 256>>>(u, M);
    finalize_stats_kernel<<<1, 256>>>(g2, bt2, M);
    gemm_tc_kernel<1, 1><<<gemmGrid, 256, SMEM_BYTES>>>(u, Wh[3], Wl[3], b2b, out, M);
}

// round 10
// speedup vs baseline: 1.2940x; 1.2940x over previous
#include <cuda_runtime.h>
#include <cuda_bf16.h>
#include <cstdint>

#define D 256
#define MAXM 100096   // >= N, multiple of 128
#define MAXE 1700000
#define SCANB 1024
#define MAXSB 128

// ---------------- scratch (device globals; no allocations) ----------------
__device__ float g_t[(size_t)MAXM * D];   // aggregated features (GEMM-a input)
__device__ float g_u[(size_t)MAXM * D];   // GEMM-a output
__device__ float g_hbuf[(size_t)MAXM * D];// conv1 output
__device__ float g_sum[D];
__device__ float g_sumsq[D];
__device__ float g_scale[D];
__device__ float g_shift[D];
// weights pre-converted to bf16 hi/lo: 4 matrices of 256x256
__device__ __nv_bfloat16 g_wh[4][D * D];
__device__ __nv_bfloat16 g_wl[4][D * D];
// CSR scratch
__device__ int g_deg[MAXM];
__device__ int g_cursor[MAXM];
__device__ int g_rowptr[MAXM + 1];
__device__ int g_col[MAXE];
__device__ int g_bsum[MAXSB];

// ---------------- BN helpers ----------------
__global__ void zero_stats_kernel() {
    g_sum[threadIdx.x] = 0.f;
    g_sumsq[threadIdx.x] = 0.f;
}

__global__ void stats_kernel(const float* __restrict__ X, int M) {
    int c = threadIdx.x;
    int rows = (M + gridDim.x - 1) / gridDim.x;
    int r0 = blockIdx.x * rows;
    int r1 = r0 + rows;
    if (r1 > M) r1 = M;
    float s = 0.f, q = 0.f;
    int r = r0;
    for (; r + 4 <= r1; r += 4) {
        float v0 = X[(size_t)(r + 0) * D + c];
        float v1 = X[(size_t)(r + 1) * D + c];
        float v2 = X[(size_t)(r + 2) * D + c];
        float v3 = X[(size_t)(r + 3) * D + c];
        s += (v0 + v1) + (v2 + v3);
        q += (v0 * v0 + v1 * v1) + (v2 * v2 + v3 * v3);
    }
    for (; r < r1; r++) {
        float v = X[(size_t)r * D + c];
        s += v;
        q += v * v;
    }
    if (r1 > r0) {
        atomicAdd(&g_sum[c], s);
        atomicAdd(&g_sumsq[c], q);
    }
}

__global__ void finalize_stats_kernel(const float* __restrict__ gamma,
                                      const float* __restrict__ beta, int M) {
    int c = threadIdx.x;
    float invM = 1.f / (float)M;
    float mu = g_sum[c] * invM;
    float var = g_sumsq[c] * invM - mu * mu;
    float sc = gamma[c] * rsqrtf(var + 1e-5f);
    g_scale[c] = sc;
    g_shift[c] = beta[c] - mu * sc;
}

// ---------------- weight pre-conversion (bf16 hi/lo split), all 4 in one ----
__global__ void convert_w_kernel(const float* __restrict__ W0,
                                 const float* __restrict__ W1,
                                 const float* __restrict__ W2,
                                 const float* __restrict__ W3) {
    const float* Ws[4] = {W0, W1, W2, W3};
    int w = blockIdx.y;
    int i = blockIdx.x * blockDim.x + threadIdx.x;  // over D*D/2 pairs
    float2 v = ((const float2*)Ws[w])[i];
    __nv_bfloat162 hh = __floats2bfloat162_rn(v.x, v.y);
    float2 f = __bfloat1622float2(hh);
    __nv_bfloat162 ll = __floats2bfloat162_rn(v.x - f.x, v.y - f.y);
    ((__nv_bfloat162*)g_wh[w])[i] = hh;
    ((__nv_bfloat162*)g_wl[w])[i] = ll;
}

// ---------------- CSR build ----------------
__global__ void zero_deg_kernel(int M) {
    int i = blockIdx.x * blockDim.x + threadIdx.x;
    if (i < M) {
        g_deg[i] = 0;
        g_cursor[i] = 0;
    }
}

__global__ void hist_kernel(const int* __restrict__ dstIdx, int E) {
    int e = blockIdx.x * blockDim.x + threadIdx.x;
    if (e < E) atomicAdd(&g_deg[dstIdx[e]], 1);
}

__global__ void scan_block_kernel(int M) {
    __shared__ int sh[SCANB];
    int i = blockIdx.x * SCANB + threadIdx.x;
    int v = (i < M) ? g_deg[i] : 0;
    sh[threadIdx.x] = v;
    __syncthreads();
    for (int off = 1; off < SCANB; off <<= 1) {
        int t = (threadIdx.x >= off) ? sh[threadIdx.x - off] : 0;
        __syncthreads();
        sh[threadIdx.x] += t;
        __syncthreads();
    }
    if (i < M) g_rowptr[i] = sh[threadIdx.x] - v;
    if (threadIdx.x == SCANB - 1) g_bsum[blockIdx.x] = sh[SCANB - 1];
}

__global__ void scan_bsum_kernel(int nb) {
    if (threadIdx.x == 0) {
        int run = 0;
        for (int i = 0; i < nb; i++) {
            int v = g_bsum[i];
            g_bsum[i] = run;
            run += v;
        }
    }
}

__global__ void scan_add_kernel(int M, int E) {
    int i = blockIdx.x * SCANB + threadIdx.x;
    if (i < M) g_rowptr[i] += g_bsum[blockIdx.x];
    if (i == 0) g_rowptr[M] = E;
}

__global__ void fill_kernel(const int* __restrict__ srcIdx,
                            const int* __restrict__ dstIdx, int E) {
    int e = blockIdx.x * blockDim.x + threadIdx.x;
    if (e >= E) return;
    int d = dstIdx[e];
    int pos = g_rowptr[d] + atomicAdd(&g_cursor[d], 1);
    g_col[pos] = srcIdx[e];
}

// ---------------- CSR aggregation ----------------
template <int BN_FOLD>
__global__ void agg_csr_kernel(const float* __restrict__ feat,
                               float* __restrict__ out, int M) {
    int node = blockIdx.x * 4 + (threadIdx.x >> 6);
    if (node >= M) return;
    int lane = threadIdx.x & 63;
    int e0 = __ldg(&g_rowptr[node]);
    int e1 = __ldg(&g_rowptr[node + 1]);
    const float4* base = (const float4*)feat;
    float4 acc = base[(size_t)node * 64 + lane];  // self term
    int e = e0;
    for (; e + 4 <= e1; e += 4) {
        int s0 = __ldg(&g_col[e + 0]);
        int s1 = __ldg(&g_col[e + 1]);
        int s2 = __ldg(&g_col[e + 2]);
        int s3 = __ldg(&g_col[e + 3]);
        float4 v0 = base[(size_t)s0 * 64 + lane];
        float4 v1 = base[(size_t)s1 * 64 + lane];
        float4 v2 = base[(size_t)s2 * 64 + lane];
        float4 v3 = base[(size_t)s3 * 64 + lane];
        acc.x += (v0.x + v1.x) + (v2.x + v3.x);
        acc.y += (v0.y + v1.y) + (v2.y + v3.y);
        acc.z += (v0.z + v1.z) + (v2.z + v3.z);
        acc.w += (v0.w + v1.w) + (v2.w + v3.w);
    }
    for (; e < e1; e++) {
        int s = __ldg(&g_col[e]);
        float4 v = base[(size_t)s * 64 + lane];
        acc.x += v.x;
        acc.y += v.y;
        acc.z += v.z;
        acc.w += v.w;
    }
    if (BN_FOLD) {
        float4 s = ((const float4*)g_scale)[lane];
        float4 sh = ((const float4*)g_shift)[lane];
        float k = (float)(1 + (e1 - e0));
        acc.x = acc.x * s.x + k * sh.x;
        acc.y = acc.y * s.y + k * sh.y;
        acc.z = acc.z * s.z + k * sh.z;
        acc.w = acc.w * s.w + k * sh.w;
    }
    ((float4*)out)[(size_t)node * 64 + lane] = acc;
}

// ---------------- tensor-core GEMM (bf16x3 split, fp32 accum) ----------------
// 128x128 tile, 512 threads (16 warps, 4x4), warp tile 32x32; sync-loop (R8 style)
#define BK 32
#define AS 40    // As row stride (elements)
#define BS 136   // Bs row stride (elements)

template <int BN_IN, int RELU>
__global__ __launch_bounds__(512, 1) void gemm_tc_kernel(
    const float* __restrict__ A, const __nv_bfloat16* __restrict__ Wh,
    const __nv_bfloat16* __restrict__ Wl, const float* __restrict__ bias,
    float* __restrict__ C, int M) {
    __shared__ __nv_bfloat16 As_h[128 * AS];
    __shared__ __nv_bfloat16 As_l[128 * AS];
    __shared__ __nv_bfloat16 Bs_h[BK * BS];
    __shared__ __nv_bfloat16 Bs_l[BK * BS];

    int bm = blockIdx.x * 128;
    int bn = blockIdx.y * 128;
    int tid = threadIdx.x;
    int lane = tid & 31;
    int wid = tid >> 5;
    int warp_m = wid >> 2;   // 0..3
    int warp_n = wid & 3;    // 0..3

    float acc[2][4][4];
#pragma unroll
    for (int i = 0; i < 2; i++)
#pragma unroll
        for (int j = 0; j < 4; j++)
#pragma unroll
            for (int r = 0; r < 4; r++) acc[i][j][r] = 0.f;

    // A loader: 4 threads per row, 8 k-floats (2 float4) each
    int a_row = tid >> 2;          // 0..127
    int a_kb = (tid & 3) * 8;      // 0,8,16,24
    bool a_valid = (bm + a_row) < M;
    // B loader: 512 threads cover 32x128 bf16 via one uint4 each per matrix
    int b_row = tid >> 4;          // 0..31
    int b_c8 = (tid & 15) * 8;     // 0..120

    uint32_t as_h_base = (uint32_t)__cvta_generic_to_shared(As_h);
    uint32_t as_l_base = (uint32_t)__cvta_generic_to_shared(As_l);
    uint32_t bs_h_base = (uint32_t)__cvta_generic_to_shared(Bs_h);
    uint32_t bs_l_base = (uint32_t)__cvta_generic_to_shared(Bs_l);

    for (int k0 = 0; k0 < D; k0 += BK) {
        // ---- load A tile (128 x BK), optional BN+relu, hi/lo split ----
        {
            const float* Ar = A + (size_t)(bm + a_row) * D + k0 + a_kb;
#pragma unroll
            for (int i = 0; i < 2; i++) {
                float4 v = a_valid ? *(const float4*)(Ar + i * 4)
                                   : make_float4(0.f, 0.f, 0.f, 0.f);
                if (BN_IN) {
                    float4 s = ((const float4*)g_scale)[((k0 + a_kb) >> 2) + i];
                    float4 sh = ((const float4*)g_shift)[((k0 + a_kb) >> 2) + i];
                    v.x = fmaxf(v.x * s.x + sh.x, 0.f);
                    v.y = fmaxf(v.y * s.y + sh.y, 0.f);
                    v.z = fmaxf(v.z * s.z + sh.z, 0.f);
                    v.w = fmaxf(v.w * s.w + sh.w, 0.f);
                }
                __nv_bfloat162 h01 = __floats2bfloat162_rn(v.x, v.y);
                __nv_bfloat162 h23 = __floats2bfloat162_rn(v.z, v.w);
                float2 f01 = __bfloat1622float2(h01);
                float2 f23 = __bfloat1622float2(h23);
                __nv_bfloat162 l01 = __floats2bfloat162_rn(v.x - f01.x, v.y - f01.y);
                __nv_bfloat162 l23 = __floats2bfloat162_rn(v.z - f23.x, v.w - f23.y);
                int off = a_row * AS + a_kb + i * 4;
                *(__nv_bfloat162*)&As_h[off] = h01;
                *(__nv_bfloat162*)&As_h[off + 2] = h23;
                *(__nv_bfloat162*)&As_l[off] = l01;
                *(__nv_bfloat162*)&As_l[off + 2] = l23;
            }
        }
        // ---- load B tile (BK x 128) directly as bf16 uint4 ----
        {
            size_t goff = (size_t)(k0 + b_row) * D + bn + b_c8;
            *(uint4*)&Bs_h[b_row * BS + b_c8] = *(const uint4*)(Wh + goff);
            *(uint4*)&Bs_l[b_row * BS + b_c8] = *(const uint4*)(Wl + goff);
        }
        __syncthreads();

#pragma unroll
        for (int k16 = 0; k16 < BK; k16 += 16) {
            uint32_t ah[2][4];
            uint32_t al[2][4];
            uint32_t bh[4][2];
            uint32_t bl[4][2];
#pragma unroll
            for (int mi = 0; mi < 2; mi++) {
                int row = warp_m * 32 + mi * 16 + (lane & 15);
                int col = k16 + ((lane >> 4) << 3);
                uint32_t ad = as_h_base + (uint32_t)(row * AS + col) * 2;
                asm volatile("ldmatrix.sync.aligned.m8n8.x4.shared.b16 {%0,%1,%2,%3}, [%4];"
                             : "=r"(ah[mi][0]), "=r"(ah[mi][1]), "=r"(ah[mi][2]), "=r"(ah[mi][3])
                             : "r"(ad));
                uint32_t ad2 = as_l_base + (uint32_t)(row * AS + col) * 2;
                asm volatile("ldmatrix.sync.aligned.m8n8.x4.shared.b16 {%0,%1,%2,%3}, [%4];"
                             : "=r"(al[mi][0]), "=r"(al[mi][1]), "=r"(al[mi][2]), "=r"(al[mi][3])
                             : "r"(ad2));
            }
#pragma unroll
            for (int ni = 0; ni < 4; ni++) {
                int row = k16 + (lane & 15);
                int col = warp_n * 32 + ni * 8;
                uint32_t bd = bs_h_base + (uint32_t)(row * BS + col) * 2;
                asm volatile("ldmatrix.sync.aligned.m8n8.x2.trans.shared.b16 {%0,%1}, [%2];"
                             : "=r"(bh[ni][0]), "=r"(bh[ni][1]) : "r"(bd));
                uint32_t bd2 = bs_l_base + (uint32_t)(row * BS + col) * 2;
                asm volatile("ldmatrix.sync.aligned.m8n8.x2.trans.shared.b16 {%0,%1}, [%2];"
                             : "=r"(bl[ni][0]), "=r"(bl[ni][1]) : "r"(bd2));
            }
#pragma unroll
            for (int mi = 0; mi < 2; mi++) {
#pragma unroll
                for (int ni = 0; ni < 4; ni++) {
                    float* d = acc[mi][ni];
                    asm volatile(
                        "mma.sync.aligned.m16n8k16.row.col.f32.bf16.bf16.f32 "
                        "{%0,%1,%2,%3}, {%4,%5,%6,%7}, {%8,%9}, {%0,%1,%2,%3};"
                        : "+f"(d[0]), "+f"(d[1]), "+f"(d[2]), "+f"(d[3])
                        : "r"(ah[mi][0]), "r"(ah[mi][1]), "r"(ah[mi][2]), "r"(ah[mi][3]),
                          "r"(bh[ni][0]), "r"(bh[ni][1]));
                    asm volatile(
                        "mma.sync.aligned.m16n8k16.row.col.f32.bf16.bf16.f32 "
                        "{%0,%1,%2,%3}, {%4,%5,%6,%7}, {%8,%9}, {%0,%1,%2,%3};"
                        : "+f"(d[0]), "+f"(d[1]), "+f"(d[2]), "+f"(d[3])
                        : "r"(ah[mi][0]), "r"(ah[mi][1]), "r"(ah[mi][2]), "r"(ah[mi][3]),
                          "r"(bl[ni][0]), "r"(bl[ni][1]));
                    asm volatile(
                        "mma.sync.aligned.m16n8k16.row.col.f32.bf16.bf16.f32 "
                        "{%0,%1,%2,%3}, {%4,%5,%6,%7}, {%8,%9}, {%0,%1,%2,%3};"
                        : "+f"(d[0]), "+f"(d[1]), "+f"(d[2]), "+f"(d[3])
                        : "r"(al[mi][0]), "r"(al[mi][1]), "r"(al[mi][2]), "r"(al[mi][3]),
                          "r"(bh[ni][0]), "r"(bh[ni][1]));
                }
            }
        }
        __syncthreads();
    }

    // ---- epilogue: bias (+relu) + store ----
#pragma unroll
    for (int mi = 0; mi < 2; mi++) {
#pragma unroll
        for (int ni = 0; ni < 4; ni++) {
            int r0 = bm + warp_m * 32 + mi * 16 + (lane >> 2);
            int c0 = bn + warp_n * 32 + ni * 8 + (lane & 3) * 2;
            float b0 = bias[c0], b1 = bias[c0 + 1];
            float* d = acc[mi][ni];
            float2 v0 = make_float2(d[0] + b0, d[1] + b1);
            float2 v1 = make_float2(d[2] + b0, d[3] + b1);
            if (RELU) {
                v0.x = fmaxf(v0.x, 0.f); v0.y = fmaxf(v0.y, 0.f);
                v1.x = fmaxf(v1.x, 0.f); v1.y = fmaxf(v1.y, 0.f);
            }
            if (r0 < M) *(float2*)&C[(size_t)r0 * D + c0] = v0;
            if (r0 + 8 < M) *(float2*)&C[(size_t)(r0 + 8) * D + c0] = v1;
        }
    }
}

// ---------------- driver ----------------
extern "C" void kernel_launch(void* const* d_in, const int* in_sizes, int n_in,
                              void* d_out, int out_size) {
    const float* x = (const float*)d_in[0];
    const int* ei = (const int*)d_in[1];   // int32 (JAX x64 disabled)
    const float* g0 = (const float*)d_in[2];
    const float* b0 = (const float*)d_in[3];
    const float* W1a = (const float*)d_in[4];
    const float* b1a = (const float*)d_in[5];
    const float* g1 = (const float*)d_in[6];
    const float* bt1 = (const float*)d_in[7];
    const float* W1b = (const float*)d_in[8];
    const float* b1b = (const float*)d_in[9];
    const float* W2a = (const float*)d_in[10];
    const float* b2a = (const float*)d_in[11];
    const float* g2 = (const float*)d_in[12];
    const float* bt2 = (const float*)d_in[13];
    const float* W2b = (const float*)d_in[14];
    const float* b2b = (const float*)d_in[15];
    float* out = (float*)d_out;

    int M = in_sizes[0] / D;
    int E = in_sizes[1] / 2;
    const int* srcI = ei;
    const int* dstI = ei + E;

    float *t, *u, *h;
    cudaGetSymbolAddress((void**)&t, g_t);
    cudaGetSymbolAddress((void**)&u, g_u);
    cudaGetSymbolAddress((void**)&h, g_hbuf);
    __nv_bfloat16 *wh, *wl;
    cudaGetSymbolAddress((void**)&wh, g_wh);
    cudaGetSymbolAddress((void**)&wl, g_wl);
    __nv_bfloat16* Wh[4] = {wh, wh + D * D, wh + 2 * D * D, wh + 3 * D * D};
    __nv_bfloat16* Wl[4] = {wl, wl + D * D, wl + 2 * D * D, wl + 3 * D * D};

    dim3 gemmGrid((M + 127) / 128, 2);
    int aggGrid = (M + 3) / 4;
    int nb = (M + SCANB - 1) / SCANB;

    // ---- pre-convert weights (one launch for all 4) ----
    convert_w_kernel<<<dim3((D * D / 2) / 256, 4), 256>>>(W1a, W1b, W2a, W2b);

    // ---- build CSR once (reused by both convs) ----
    zero_deg_kernel<<<(M + 255) / 256, 256>>>(M);
    hist_kernel<<<(E + 255) / 256, 256>>>(dstI, E);
    scan_block_kernel<<<nb, SCANB>>>(M);
    scan_bsum_kernel<<<1, 32>>>(nb);
    scan_add_kernel<<<nb, SCANB>>>(M, E);
    fill_kernel<<<(E + 255) / 256, 256>>>(srcI, dstI, E);

    // ---- BN0 stats on x; agg with BN folded (linearity) ----
    zero_stats_kernel<<<1, 256>>>();
    stats_kernel<<<512, 256>>>(x, M);
    finalize_stats_kernel<<<1, 256>>>(g0, b0, M);
    agg_csr_kernel<1><<<aggGrid, 256>>>(x, t, M);                       // t = BN0-agg(x)

    // ---- conv1 ----
    gemm_tc_kernel<0, 0><<<gemmGrid, 512>>>(t, Wh[0], Wl[0], b1a, u, M);
    zero_stats_kernel<<<1, 256>>>();
    stats_kernel<<<512, 256>>>(u, M);
    finalize_stats_kernel<<<1, 256>>>(g1, bt1, M);
    gemm_tc_kernel<1, 1><<<gemmGrid, 512>>>(u, Wh[1], Wl[1], b1b, h, M);

    // ---- conv2 ----
    agg_csr_kernel<0><<<aggGrid, 256>>>(h, t, M);                       // t = h + Σh
    gemm_tc_kernel<0, 0><<<gemmGrid, 512>>>(t, Wh[2], Wl[2], b2a, u, M);
    zero_stats_kernel<<<1, 256>>>();
    stats_kernel<<<512, 256>>>(u, M);
    finalize_stats_kernel<<<1, 256>>>(g2, bt2, M);
    gemm_tc_kernel<1, 1><<<gemmGrid, 512>>>(u, Wh[3], Wl[3], b2b, out, M);
}